// round 13
// baseline (speedup 1.0000x reference)
#include <cuda_runtime.h>

#define NROWS   512      // 16 * 32
#define NP      256      // particles per row
#define OD      10       // OBS_DIM
#define AD      4        // ACTION_DIM
#define ROW_LEN 2564
#define NBLK    512      // one block per row (both directions fused)
#define C_BIAS  32.0f

__device__ float g_partial[NBLK];
__device__ float g_action[NROWS];
__device__ float g_a0[NROWS];
__device__ int   g_cnt;          // zero-init; last block resets it each run

__device__ __forceinline__ unsigned umin_(unsigned a, unsigned b) { return a < b ? a : b; }

__global__ __launch_bounds__(256, 4)
void chamfer_kernel(const float* __restrict__ preds,
                    const float* __restrict__ targ,
                    float* __restrict__ out) {
    const int r = blockIdx.x;        // row = b*32 + h
    const int t = threadIdx.x;       // query column (0..255), both directions

    __shared__ float  obs_s[NP * OD];   // 10 KB
    __shared__ float  obt_s[NP * OD];   // 10 KB
    __shared__ float4 fA[NP];           // obs  feats (dims 5..8)   4 KB
    __shared__ float4 fB[NP];           // targ feats               4 KB
    __shared__ float2 hA2[NP / 2];      // obs  biased half-norms   1 KB
    __shared__ float2 hB2[NP / 2];      // targ biased half-norms   1 KB
    __shared__ float  red[256];
    __shared__ int    s_last;

    // ---- stage both rows (float4: base (r*2564+4)*4 is 16B-aligned) ----
    const float4* pr4 = (const float4*)(preds + (size_t)r * ROW_LEN + AD);
    const float4* tg4 = (const float4*)(targ  + (size_t)r * ROW_LEN + AD);
    #pragma unroll
    for (int i = t; i < NP * OD / 4; i += 256) {
        ((float4*)obs_s)[i] = pr4[i];
        ((float4*)obt_s)[i] = tg4[i];
    }
    __syncthreads();

    // ---- pack candidate feats + biased half-norms (score = C + 0.5|c|^2 - c.q) ----
    {
        float ox = obs_s[t*OD+5], oy = obs_s[t*OD+6], oz = obs_s[t*OD+7], ow = obs_s[t*OD+8];
        float tx = obt_s[t*OD+5], ty = obt_s[t*OD+6], tz = obt_s[t*OD+7], tw = obt_s[t*OD+8];
        fA[t] = make_float4(ox, oy, oz, ow);
        fB[t] = make_float4(tx, ty, tz, tw);
        ((float*)hA2)[t] = C_BIAS + 0.5f * (ox*ox + oy*oy + oz*oz + ow*ow);
        ((float*)hB2)[t] = C_BIAS + 0.5f * (tx*tx + ty*ty + tz*tz + tw*tw);
    }
    __syncthreads();

    // ---- this thread's two queries ----
    // dir0: query = targ[t], candidates = obs  (idx1, weight 3)
    // dir1: query = obs[t],  candidates = targ (idx2, weight 1)
    const float4 qa = fB[t];    // targ query feats
    const float4 qb = fA[t];    // obs  query feats
    const float q0x = -qa.x, q0y = -qa.y, q0z = -qa.z, q0w = -qa.w;
    const float q1x = -qb.x, q1y = -qb.y, q1z = -qb.z, q1w = -qb.w;

    // key = (score_bits & ~0xFF) | k  (score > 0 -> unsigned order == float order)
    // even/odd parity accumulators carry the TRUE 8-bit index -> final umin is exact
    unsigned a0e = 0xFFFFFFFFu, a0o = 0xFFFFFFFFu;   // dir0
    unsigned a1e = 0xFFFFFFFFu, a1o = 0xFFFFFFFFu;   // dir1
    #pragma unroll 2
    for (int k = 0; k < NP; k += 2) {
        const float4 cA0 = fA[k];        // LDS.128
        const float4 cA1 = fA[k + 1];
        const float4 cB0 = fB[k];
        const float4 cB1 = fB[k + 1];
        const float2 ha = hA2[k >> 1];   // LDS.64
        const float2 hb = hB2[k >> 1];

        // dir0: scan obs candidates against targ query  (4 indep FFMA chains)
        float s0e = fmaf(cA0.x, q0x, ha.x);
        float s0o = fmaf(cA1.x, q0x, ha.y);
        s0e = fmaf(cA0.y, q0y, s0e);  s0o = fmaf(cA1.y, q0y, s0o);
        s0e = fmaf(cA0.z, q0z, s0e);  s0o = fmaf(cA1.z, q0z, s0o);
        s0e = fmaf(cA0.w, q0w, s0e);  s0o = fmaf(cA1.w, q0w, s0o);

        // dir1: scan targ candidates against obs query
        float s1e = fmaf(cB0.x, q1x, hb.x);
        float s1o = fmaf(cB1.x, q1x, hb.y);
        s1e = fmaf(cB0.y, q1y, s1e);  s1o = fmaf(cB1.y, q1y, s1o);
        s1e = fmaf(cB0.z, q1z, s1e);  s1o = fmaf(cB1.z, q1z, s1o);
        s1e = fmaf(cB0.w, q1w, s1e);  s1o = fmaf(cB1.w, q1w, s1o);

        const unsigned ke = (unsigned)k, ko = (unsigned)(k + 1);
        a0e = umin_(a0e, (__float_as_uint(s0e) & 0xFFFFFF00u) | ke);
        a0o = umin_(a0o, (__float_as_uint(s0o) & 0xFFFFFF00u) | ko);
        a1e = umin_(a1e, (__float_as_uint(s1e) & 0xFFFFFF00u) | ke);
        a1o = umin_(a1o, (__float_as_uint(s1o) & 0xFFFFFF00u) | ko);
    }
    const int i0 = (int)(umin_(a0e, a0o) & 0xFFu);   // nearest obs  for targ[t]
    const int i1 = (int)(umin_(a1e, a1o) & 0xFFu);   // nearest targ for obs[t]

    // ---- L1 gather over all 10 dims (full fp32) ----
    float s1f = 0.f, s2f = 0.f;
    #pragma unroll
    for (int d = 0; d < OD; ++d) {
        s1f += fabsf(obs_s[i0 * OD + d] - obt_s[t * OD + d]);   // particle_dist1, w=3
        s2f += fabsf(obt_s[i1 * OD + d] - obs_s[t * OD + d]);   // particle_dist2, w=1
    }
    red[t] = 3.0f * s1f + s2f;
    __syncthreads();
    #pragma unroll
    for (int off = 128; off > 0; off >>= 1) {
        if (t < off) red[t] += red[t + off];
        __syncthreads();
    }

    if (t == 0) {
        g_partial[r] = red[0];
        const float* pr = preds + (size_t)r * ROW_LEN;
        const float* tg = targ  + (size_t)r * ROW_LEN;
        float al1 = 0.f;
        #pragma unroll
        for (int d = 0; d < AD; ++d) al1 += fabsf(pr[d] - tg[d]);
        al1 *= 0.25f;
        const int h = r & 31;
        g_action[r] = (h == 1) ? al1 * 10.0f : al1;
        g_a0[r]     = (h == 1) ? al1 : 0.0f;
        __threadfence();
        const int ticket = atomicAdd(&g_cnt, 1);
        s_last = (ticket == NBLK - 1) ? 1 : 0;
    }
    __syncthreads();

    // ---- fused final reduction: last block to finish does it ----
    if (s_last) {
        float c = (t < NROWS) ? g_partial[t] + g_partial[t + 256] : 0.f;
        // NROWS == 512: each of 256 threads sums 2 entries
        red[t] = c;
        __syncthreads();
        #pragma unroll
        for (int off = 128; off > 0; off >>= 1) {
            if (t < off) red[t] += red[t + off];
            __syncthreads();
        }
        const float chamfer_total = red[0];
        __syncthreads();

        float a = g_action[t] + g_action[t + 256];
        red[t] = a;
        __syncthreads();
        #pragma unroll
        for (int off = 128; off > 0; off >>= 1) {
            if (t < off) red[t] += red[t + off];
            __syncthreads();
        }
        const float action_total = red[0];
        __syncthreads();

        float z = g_a0[t] + g_a0[t + 256];
        red[t] = z;
        __syncthreads();
        #pragma unroll
        for (int off = 128; off > 0; off >>= 1) {
            if (t < off) red[t] += red[t + off];
            __syncthreads();
        }
        const float a0_total = red[0];

        if (t == 0) {
            // chamfer mean = total / (4 * 512*256*10)
            out[0] = action_total * (1.0f / NROWS) + chamfer_total * (1.0f / 5242880.0f);
            out[1] = a0_total * (1.0f / 16.0f);
            g_cnt  = 0;   // reset for next graph replay
        }
    }
}

extern "C" void kernel_launch(void* const* d_in, const int* in_sizes, int n_in,
                              void* d_out, int out_size) {
    const float* preds = (const float*)d_in[0];
    const float* targ  = (const float*)d_in[1];
    chamfer_kernel<<<NBLK, 256>>>(preds, targ, (float*)d_out);
}

// round 16
// speedup vs baseline: 1.3098x; 1.3098x over previous
#include <cuda_runtime.h>

#define NROWS   512      // 16 * 32
#define NP      256      // particles per row
#define OD      10       // OBS_DIM
#define AD      4        // ACTION_DIM
#define ROW_LEN 2564
#define NBLK    1024     // (row, dir) blocks
#define C_BIAS  32.0f

__device__ float g_partial[NBLK];
__device__ float g_action[NROWS];
__device__ float g_a0[NROWS];
__device__ int   g_cnt;          // zero-init; last block resets it each run

typedef unsigned long long ull;

__device__ __forceinline__ ull pk2(float a, float b) {
    ull r; asm("mov.b64 %0, {%1, %2};" : "=l"(r) : "f"(a), "f"(b)); return r;
}
__device__ __forceinline__ ull fma2_(ull a, ull b, ull c) {
    ull r; asm("fma.rn.f32x2 %0, %1, %2, %3;" : "=l"(r) : "l"(a), "l"(b), "l"(c)); return r;
}
__device__ __forceinline__ unsigned umin_(unsigned a, unsigned b) { return a < b ? a : b; }
__device__ __forceinline__ unsigned lo32(ull s) { return (unsigned)s; }
__device__ __forceinline__ unsigned hi32(ull s) { return (unsigned)(s >> 32); }

__global__ __launch_bounds__(128, 7)
void chamfer_kernel(const float* __restrict__ preds,
                    const float* __restrict__ targ,
                    float* __restrict__ out) {
    const int blk = blockIdx.x;
    const int r   = blk >> 1;        // row = b*32 + h
    const int dir = blk & 1;         // 0: candidates=obs, queries=targ (idx1, w=3); 1: swapped
    const int t   = threadIdx.x;     // 0..127; queries t and t+128

    __shared__ float obs_s[NP * OD];        // 10 KB
    __shared__ float obt_s[NP * OD];        // 10 KB
    // SoA 4-candidate blocks, f32x2-pair layout: {(c0,c1),(c2,c3)} per ulonglong2
    __shared__ ulonglong2 sx[NP/4], sy[NP/4], sz[NP/4], sw_[NP/4], sh[NP/4];  // 5 KB
    __shared__ float red[128];
    __shared__ int s_last;

    // ---- stage both rows (float4: base (r*2564+4)*4 is 16B-aligned) ----
    const float4* pr4 = (const float4*)(preds + (size_t)r * ROW_LEN + AD);
    const float4* tg4 = (const float4*)(targ  + (size_t)r * ROW_LEN + AD);
    #pragma unroll
    for (int i = t; i < NP * OD / 4; i += 128) {
        ((float4*)obs_s)[i] = pr4[i];
        ((float4*)obt_s)[i] = tg4[i];
    }
    __syncthreads();

    const float* scan = dir ? obt_s : obs_s;   // candidates (argmin over these)
    const float* mine = dir ? obs_s : obt_s;   // queries

    // ---- pack 4-candidate SoA blocks (t < 64 each builds one block) ----
    if (t < NP / 4) {
        const int c = 4 * t;
        float x0 = scan[(c+0)*OD+5], y0 = scan[(c+0)*OD+6], z0 = scan[(c+0)*OD+7], w0 = scan[(c+0)*OD+8];
        float x1 = scan[(c+1)*OD+5], y1 = scan[(c+1)*OD+6], z1 = scan[(c+1)*OD+7], w1 = scan[(c+1)*OD+8];
        float x2 = scan[(c+2)*OD+5], y2 = scan[(c+2)*OD+6], z2 = scan[(c+2)*OD+7], w2 = scan[(c+2)*OD+8];
        float x3 = scan[(c+3)*OD+5], y3 = scan[(c+3)*OD+6], z3 = scan[(c+3)*OD+7], w3 = scan[(c+3)*OD+8];
        sx[t]  = make_ulonglong2(pk2(x0, x1), pk2(x2, x3));
        sy[t]  = make_ulonglong2(pk2(y0, y1), pk2(y2, y3));
        sz[t]  = make_ulonglong2(pk2(z0, z1), pk2(z2, z3));
        sw_[t] = make_ulonglong2(pk2(w0, w1), pk2(w2, w3));
        sh[t]  = make_ulonglong2(
            pk2(C_BIAS + 0.5f*(x0*x0 + y0*y0 + z0*z0 + w0*w0),
                C_BIAS + 0.5f*(x1*x1 + y1*y1 + z1*z1 + w1*w1)),
            pk2(C_BIAS + 0.5f*(x2*x2 + y2*y2 + z2*z2 + w2*w2),
                C_BIAS + 0.5f*(x3*x3 + y3*y3 + z3*z3 + w3*w3)));
    }
    __syncthreads();

    // ---- two queries per thread ----
    const int q0 = t, q1 = t + 128;
    const float a0x = mine[q0*OD+5], a0y = mine[q0*OD+6], a0z = mine[q0*OD+7], a0w = mine[q0*OD+8];
    const float a1x = mine[q1*OD+5], a1y = mine[q1*OD+6], a1z = mine[q1*OD+7], a1w = mine[q1*OD+8];
    const ull n0x = pk2(-a0x,-a0x), n0y = pk2(-a0y,-a0y), n0z = pk2(-a0z,-a0z), n0w = pk2(-a0w,-a0w);
    const ull n1x = pk2(-a1x,-a1x), n1y = pk2(-a1y,-a1y), n1z = pk2(-a1z,-a1z), n1w = pk2(-a1w,-a1w);

    // score = C + 0.5|c|^2 - c.q  (> 0 -> uint order == float order)
    // within-pair winner via 1 umin on raw bits; cross-pair key = (bits & ~0x7F) | pairIdx
    unsigned best0 = 0xFFFFFFFFu, best1 = 0xFFFFFFFFu;
    #pragma unroll 2
    for (int b = 0; b < NP / 4; ++b) {
        const ulonglong2 X = sx[b];    // 5x LDS.128 broadcast
        const ulonglong2 Y = sy[b];
        const ulonglong2 Z = sz[b];
        const ulonglong2 W = sw_[b];
        const ulonglong2 H = sh[b];

        // query 0, pairs (2b) and (2b+1)
        ull sA = fma2_(X.x, n0x, H.x);
        ull sB = fma2_(X.y, n0x, H.y);
        sA = fma2_(Y.x, n0y, sA);  sB = fma2_(Y.y, n0y, sB);
        sA = fma2_(Z.x, n0z, sA);  sB = fma2_(Z.y, n0z, sB);
        sA = fma2_(W.x, n0w, sA);  sB = fma2_(W.y, n0w, sB);
        // query 1
        ull sC = fma2_(X.x, n1x, H.x);
        ull sD = fma2_(X.y, n1x, H.y);
        sC = fma2_(Y.x, n1y, sC);  sD = fma2_(Y.y, n1y, sD);
        sC = fma2_(Z.x, n1z, sC);  sD = fma2_(Z.y, n1z, sD);
        sC = fma2_(W.x, n1w, sC);  sD = fma2_(W.y, n1w, sD);

        const unsigned p0 = 2u * b, p1 = 2u * b + 1u;
        best0 = umin_(best0, (umin_(lo32(sA), hi32(sA)) & 0xFFFFFF80u) | p0);
        best0 = umin_(best0, (umin_(lo32(sB), hi32(sB)) & 0xFFFFFF80u) | p1);
        best1 = umin_(best1, (umin_(lo32(sC), hi32(sC)) & 0xFFFFFF80u) | p0);
        best1 = umin_(best1, (umin_(lo32(sD), hi32(sD)) & 0xFFFFFF80u) | p1);
    }

    // ---- parity fixup: recompute winning pair exactly (bit-identical chain) ----
    int i0, i1;
    {
        const int p = (int)(best0 & 0x7Fu);
        const int c = 2 * p;
        float he = ((const float*)sh)[ (p>>1)*4 + (p&1)*2 + 0 ];
        float ho = ((const float*)sh)[ (p>>1)*4 + (p&1)*2 + 1 ];
        float se = fmaf(scan[(c+0)*OD+5], -a0x, he);
        float so = fmaf(scan[(c+1)*OD+5], -a0x, ho);
        se = fmaf(scan[(c+0)*OD+6], -a0y, se);  so = fmaf(scan[(c+1)*OD+6], -a0y, so);
        se = fmaf(scan[(c+0)*OD+7], -a0z, se);  so = fmaf(scan[(c+1)*OD+7], -a0z, so);
        se = fmaf(scan[(c+0)*OD+8], -a0w, se);  so = fmaf(scan[(c+1)*OD+8], -a0w, so);
        i0 = c + (__float_as_uint(so) < __float_as_uint(se) ? 1 : 0);
    }
    {
        const int p = (int)(best1 & 0x7Fu);
        const int c = 2 * p;
        float he = ((const float*)sh)[ (p>>1)*4 + (p&1)*2 + 0 ];
        float ho = ((const float*)sh)[ (p>>1)*4 + (p&1)*2 + 1 ];
        float se = fmaf(scan[(c+0)*OD+5], -a1x, he);
        float so = fmaf(scan[(c+1)*OD+5], -a1x, ho);
        se = fmaf(scan[(c+0)*OD+6], -a1y, se);  so = fmaf(scan[(c+1)*OD+6], -a1y, so);
        se = fmaf(scan[(c+0)*OD+7], -a1z, se);  so = fmaf(scan[(c+1)*OD+7], -a1z, so);
        se = fmaf(scan[(c+0)*OD+8], -a1w, se);  so = fmaf(scan[(c+1)*OD+8], -a1w, so);
        i1 = c + (__float_as_uint(so) < __float_as_uint(se) ? 1 : 0);
    }

    // ---- L1 gather over all 10 dims (full fp32) ----
    float s1f = 0.f, s2f = 0.f;
    #pragma unroll
    for (int d = 0; d < OD; ++d) {
        s1f += fabsf(scan[i0 * OD + d] - mine[q0 * OD + d]);
        s2f += fabsf(scan[i1 * OD + d] - mine[q1 * OD + d]);
    }
    const float w = dir ? 1.0f : 3.0f;   // TARGET_WEIGHT on the idx1 direction
    red[t] = w * (s1f + s2f);
    __syncthreads();
    #pragma unroll
    for (int off = 64; off > 0; off >>= 1) {
        if (t < off) red[t] += red[t + off];
        __syncthreads();
    }

    if (t == 0) {
        g_partial[blk] = red[0];
        if (dir == 0) {
            const float* pr = preds + (size_t)r * ROW_LEN;
            const float* tg = targ  + (size_t)r * ROW_LEN;
            float al1 = 0.f;
            #pragma unroll
            for (int d = 0; d < AD; ++d) al1 += fabsf(pr[d] - tg[d]);
            al1 *= 0.25f;
            const int h = r & 31;
            g_action[r] = (h == 1) ? al1 * 10.0f : al1;
            g_a0[r]     = (h == 1) ? al1 : 0.0f;
        }
        __threadfence();
        const int ticket = atomicAdd(&g_cnt, 1);
        s_last = (ticket == NBLK - 1) ? 1 : 0;
    }
    __syncthreads();

    // ---- fused final reduction: last block to finish does it ----
    if (s_last) {
        float c = 0.f;
        for (int i = t; i < NBLK; i += 128) c += g_partial[i];
        red[t] = c;
        __syncthreads();
        #pragma unroll
        for (int off = 64; off > 0; off >>= 1) {
            if (t < off) red[t] += red[t + off];
            __syncthreads();
        }
        const float chamfer_total = red[0];
        __syncthreads();

        float a = 0.f;
        for (int i = t; i < NROWS; i += 128) a += g_action[i];
        red[t] = a;
        __syncthreads();
        #pragma unroll
        for (int off = 64; off > 0; off >>= 1) {
            if (t < off) red[t] += red[t + off];
            __syncthreads();
        }
        const float action_total = red[0];
        __syncthreads();

        float z = 0.f;
        for (int i = t; i < NROWS; i += 128) z += g_a0[i];
        red[t] = z;
        __syncthreads();
        #pragma unroll
        for (int off = 64; off > 0; off >>= 1) {
            if (t < off) red[t] += red[t + off];
            __syncthreads();
        }
        const float a0_total = red[0];

        if (t == 0) {
            // chamfer mean = total / (4 * 512*256*10)
            out[0] = action_total * (1.0f / NROWS) + chamfer_total * (1.0f / 5242880.0f);
            out[1] = a0_total * (1.0f / 16.0f);
            g_cnt  = 0;   // reset for next graph replay
        }
    }
}

extern "C" void kernel_launch(void* const* d_in, const int* in_sizes, int n_in,
                              void* d_out, int out_size) {
    const float* preds = (const float*)d_in[0];
    const float* targ  = (const float*)d_in[1];
    chamfer_kernel<<<NBLK, 128>>>(preds, targ, (float*)d_out);
}